// round 4
// baseline (speedup 1.0000x reference)
#include <cuda_runtime.h>
#include <cstdint>

typedef unsigned long long u64;
#define NTOT 65536
#define BATCH 2

__device__ __align__(16) float g_qkv1[(size_t)BATCH*384*NTOT];
__device__ __align__(16) float g_sa  [(size_t)BATCH*NTOT];
__device__ __align__(16) float g_v2  [(size_t)BATCH*128*NTOT];
__device__ __align__(16) float g_z   [(size_t)BATCH*128*NTOT];
__device__ float g_S[4096];
__device__ float g_ssq_q[256];
__device__ float g_ssq_k[256];
__device__ float g_sumv[256];
__device__ float g_attn[4096];
__device__ float g_spec[256];
__device__ __align__(16) u64 g_wq2[128*384];
__device__ __align__(16) u64 g_wp2[128*128];

__device__ __forceinline__ void fma2(u64 &d, u64 a, u64 b){
    asm("fma.rn.f32x2 %0, %1, %2, %0;" : "+l"(d) : "l"(a), "l"(b));
}
__device__ __forceinline__ float2 unpack2(u64 v){
    float2 r; asm("mov.b64 {%0, %1}, %2;" : "=f"(r.x), "=f"(r.y) : "l"(v)); return r;
}
__device__ __forceinline__ void cp_async16(void* sdst, const void* gsrc){
    unsigned s = (unsigned)__cvta_generic_to_shared(sdst);
    asm volatile("cp.async.cg.shared.global [%0], [%1], 16;" :: "r"(s), "l"(gsrc));
}
__device__ __forceinline__ void cp_commit(){ asm volatile("cp.async.commit_group;"); }
__device__ __forceinline__ void cp_wait0(){ asm volatile("cp.async.wait_group 0;"); }
__device__ __forceinline__ float gelu_exact(float x){
    return 0.5f * x * (1.0f + erff(x * 0.70710678118654752f));
}
__device__ __forceinline__ float conv_row(int valid, const float* rowbase, int col,
                                          float w0, float w1, float w2){
    if (!valid) return 0.f;
    float a = __ldg(rowbase + col);
    float l = __shfl_up_sync(0xffffffffu, a, 1);
    float r = __shfl_down_sync(0xffffffffu, a, 1);
    int lane = col & 31;
    if (lane == 0)  l = (col > 0)   ? __ldg(rowbase + col - 1) : 0.f;
    if (lane == 31) r = (col < 255) ? __ldg(rowbase + col + 1) : 0.f;
    return w0 * l + w1 * a + w2 * r;
}

__global__ void k_prep(const float* __restrict__ qkv_w, const float* __restrict__ proj_w){
    int idx = blockIdx.x * 256 + threadIdx.x;
    if (idx < 49152){
        int o = idx % 384, i = idx / 384;
        unsigned b = __float_as_uint(qkv_w[o*128 + i]);
        g_wq2[idx] = ((u64)b << 32) | (u64)b;
    } else if (idx < 65536){
        int k = idx - 49152;
        int i = k >> 7, o = k & 127;
        unsigned b = __float_as_uint(proj_w[o*128 + i]);
        g_wp2[k] = ((u64)b << 32) | (u64)b;
    } else {
        int j = idx - 65536;
        if (j < 4096) g_S[j] = 0.f;
        else if (j < 4352) g_ssq_q[j-4096] = 0.f;
        else if (j < 4608) g_ssq_k[j-4352] = 0.f;
        else if (j < 4864) g_sumv [j-4608] = 0.f;
    }
}

__global__ void __launch_bounds__(256) k_sa(const float* __restrict__ y,
                                            const float* __restrict__ w1,
                                            const float* __restrict__ w2,
                                            const float* __restrict__ w3){
    __shared__ float sW1[128][16];
    __shared__ float sW2[16][16];
    __shared__ float sW3[16];
    int tid = threadIdx.x;
    int b = blockIdx.y;
    for (int i = tid; i < 2048; i += 256){ int c = i >> 4, j = i & 15; sW1[c][j] = w1[j*128 + c]; }
    (&sW2[0][0])[tid] = w2[tid];
    if (tid < 16) sW3[tid] = w3[tid];
    __syncthreads();

    int n0 = (blockIdx.x * 256 + tid) * 4;
    float acc[4][16];
#pragma unroll
    for (int p = 0; p < 4; p++)
#pragma unroll
        for (int j = 0; j < 16; j++) acc[p][j] = 0.f;

    const float* yb = y + (size_t)b * 128 * NTOT + n0;
    for (int c = 0; c < 128; c++){
        float4 yv = *(const float4*)(yb + (size_t)c * NTOT);
#pragma unroll
        for (int j = 0; j < 16; j++){
            float w = sW1[c][j];
            acc[0][j] += w * yv.x; acc[1][j] += w * yv.y;
            acc[2][j] += w * yv.z; acc[3][j] += w * yv.w;
        }
    }
    float out[4];
#pragma unroll
    for (int p = 0; p < 4; p++){
        float t2[16];
#pragma unroll
        for (int i = 0; i < 16; i++){
            float s = 0.f;
#pragma unroll
            for (int j = 0; j < 16; j++) s += sW2[i][j] * fmaxf(acc[p][j], 0.f);
            t2[i] = fmaxf(s, 0.f);
        }
        float s3 = 0.f;
#pragma unroll
        for (int j = 0; j < 16; j++) s3 += sW3[j] * t2[j];
        out[p] = 1.f / (1.f + expf(-s3));
    }
    *(float4*)(g_sa + (size_t)b * NTOT + n0) = make_float4(out[0], out[1], out[2], out[3]);
}

// C[M,N] = W[M,128] @ X[128,N] per batch; FFMA2 register tile 8x8, cp.async double buffer
__global__ void __launch_bounds__(256, 2) k_gemm(const u64* __restrict__ w2,
                                                 const float* __restrict__ X,
                                                 float* __restrict__ C, int M){
    __shared__ u64 ws[2][16][128];
    __shared__ u64 xs[2][16][64];

    int tid = threadIdx.x;
    int b = blockIdx.z;
    int obase = blockIdx.y * 128;
    int nbase = blockIdx.x * 128;
    const float* x = X + (size_t)b * 128 * NTOT;
    float* c = C + (size_t)b * M * NTOT;
    int to8 = (tid >> 4) * 8;
    int tn4 = (tid & 15) * 4;

    auto load_chunk = [&](int kc, int buf){
#pragma unroll
        for (int t = 0; t < 4; t++){
            int e = t * 256 + tid;
            int k = e >> 6;
            int o = (2 * e) & 127;
            cp_async16(&ws[buf][k][o], w2 + (size_t)(kc*16 + k) * M + obase + o);
        }
#pragma unroll
        for (int t = 0; t < 2; t++){
            int e = t * 256 + tid;
            int k = e >> 5;
            int p = (2 * e) & 63;
            cp_async16(&xs[buf][k][p], x + (size_t)(kc*16 + k) * NTOT + nbase + 2*p);
        }
        cp_commit();
    };

    u64 acc[8][4];
#pragma unroll
    for (int o = 0; o < 8; o++)
#pragma unroll
        for (int p = 0; p < 4; p++) acc[o][p] = 0ULL;

    load_chunk(0, 0);
    cp_wait0(); __syncthreads();

    for (int kc = 0; kc < 8; kc++){
        int buf = kc & 1;
        if (kc < 7) load_chunk(kc + 1, buf ^ 1);
#pragma unroll
        for (int k = 0; k < 16; k++){
            u64 wv[8], xv[4];
#pragma unroll
            for (int j = 0; j < 4; j++){
                ulonglong2 t = *(const ulonglong2*)&ws[buf][k][to8 + 2*j];
                wv[2*j] = t.x; wv[2*j+1] = t.y;
            }
            {
                ulonglong2 t0 = *(const ulonglong2*)&xs[buf][k][tn4];
                ulonglong2 t1 = *(const ulonglong2*)&xs[buf][k][tn4 + 2];
                xv[0] = t0.x; xv[1] = t0.y; xv[2] = t1.x; xv[3] = t1.y;
            }
#pragma unroll
            for (int o = 0; o < 8; o++)
#pragma unroll
                for (int p = 0; p < 4; p++)
                    fma2(acc[o][p], wv[o], xv[p]);
        }
        if (kc < 7){ cp_wait0(); __syncthreads(); }
    }

#pragma unroll
    for (int o = 0; o < 8; o++){
        float2 f0 = unpack2(acc[o][0]), f1 = unpack2(acc[o][1]);
        float2 f2 = unpack2(acc[o][2]), f3 = unpack2(acc[o][3]);
        float* dst = c + (size_t)(obase + to8 + o) * NTOT + nbase + (tid & 15) * 8;
        *(float4*)(dst)     = make_float4(f0.x, f0.y, f1.x, f1.y);
        *(float4*)(dst + 4) = make_float4(f2.x, f2.y, f3.x, f3.y);
    }
}

// fused dwconv3x3 + sa gate + (S=q.k^T, ||q||^2, ||k||^2, sum v) reductions + v write
__global__ void __launch_bounds__(256) k2_dw(const float* __restrict__ qkv_dw_w){
    int tid = threadIdx.x;
    int r = blockIdx.x, h = blockIdx.y, b = blockIdx.z;
    __shared__ float qs[16][257];
    __shared__ float ks[16][257];
    __shared__ float sdw[48][9];
    __shared__ float s_sa[256];
    __shared__ float s_ssq_q[16], s_ssq_k[16], s_vsum[16];

    s_sa[tid] = g_sa[(size_t)b * NTOT + r*256 + tid];
    for (int idx = tid; idx < 432; idx += 256){
        int lc = idx / 9, j = idx % 9;
        int ch = (lc < 16) ? (h*16 + lc) : (lc < 32 ? (128 + h*16 + (lc-16)) : (256 + h*16 + (lc-32)));
        sdw[lc][j] = qkv_dw_w[ch*9 + j];
    }
    if (tid < 16){ s_ssq_q[tid] = 0.f; s_ssq_k[tid] = 0.f; s_vsum[tid] = 0.f; }
    __syncthreads();

    int lane = tid & 31;
    for (int lc = 0; lc < 48; lc++){
        int ch = (lc < 16) ? (h*16 + lc) : (lc < 32 ? (128 + h*16 + (lc-16)) : (256 + h*16 + (lc-32)));
        const float* base = g_qkv1 + ((size_t)b*384 + ch) * NTOT;
        float v = conv_row(r > 0,   base + (size_t)(r-1)*256, tid, sdw[lc][0], sdw[lc][1], sdw[lc][2])
                + conv_row(1,       base + (size_t)r*256,     tid, sdw[lc][3], sdw[lc][4], sdw[lc][5])
                + conv_row(r < 255, base + (size_t)(r+1)*256, tid, sdw[lc][6], sdw[lc][7], sdw[lc][8]);
        if (lc < 16){
            v *= s_sa[tid];
            qs[lc][tid] = v;
            float sq = v * v;
#pragma unroll
            for (int o = 16; o; o >>= 1) sq += __shfl_down_sync(0xffffffffu, sq, o);
            if (lane == 0) atomicAdd(&s_ssq_q[lc], sq);
        } else if (lc < 32){
            ks[lc-16][tid] = v;
            float sq = v * v;
#pragma unroll
            for (int o = 16; o; o >>= 1) sq += __shfl_down_sync(0xffffffffu, sq, o);
            if (lane == 0) atomicAdd(&s_ssq_k[lc-16], sq);
        } else {
            g_v2[((size_t)b*128 + h*16 + (lc-32)) * NTOT + r*256 + tid] = v;
            float sv = v;
#pragma unroll
            for (int o = 16; o; o >>= 1) sv += __shfl_down_sync(0xffffffffu, sv, o);
            if (lane == 0) atomicAdd(&s_vsum[lc-32], sv);
        }
    }
    __syncthreads();

    int c = tid >> 4, d = tid & 15;
    float s = 0.f;
#pragma unroll 4
    for (int col = 0; col < 256; col++) s += qs[c][col] * ks[d][col];
    atomicAdd(&g_S[((b*8 + h)*16 + c)*16 + d], s);

    if (tid < 16){
        atomicAdd(&g_ssq_q[b*128 + h*16 + tid], s_ssq_q[tid]);
        atomicAdd(&g_ssq_k[b*128 + h*16 + tid], s_ssq_k[tid]);
        atomicAdd(&g_sumv [b*128 + h*16 + tid], s_vsum[tid]);
    }
}

// softmax + spectral MLP (one block, 256 threads)
__global__ void k4_small(const float* __restrict__ sp_w1, const float* __restrict__ sp_w2,
                         const float* __restrict__ sp_w3, const float* __restrict__ temp){
    __shared__ float pooled[2][128];
    __shared__ float t1s[2][16], t2s[2][16];
    int t = threadIdx.x;
    int b = t >> 7, row = t & 127, h = row >> 4, c = row & 15;

    float nq = fmaxf(sqrtf(g_ssq_q[b*128 + row]), 1e-12f);
    float tmp = temp[h];
    float logits[16];
    float mx = -1e30f;
#pragma unroll
    for (int d = 0; d < 16; d++){
        float nk = fmaxf(sqrtf(g_ssq_k[b*128 + h*16 + d]), 1e-12f);
        float L = g_S[((b*8 + h)*16 + c)*16 + d] / (nq * nk) * tmp;
        logits[d] = L; mx = fmaxf(mx, L);
    }
    float se = 0.f;
#pragma unroll
    for (int d = 0; d < 16; d++){ float e = expf(logits[d] - mx); logits[d] = e; se += e; }
    float inv = 1.f / se;
    float pool = 0.f;
#pragma unroll
    for (int d = 0; d < 16; d++){
        float a = logits[d] * inv;
        g_attn[b*2048 + (h*16 + c)*16 + d] = a;
        pool += a * g_sumv[b*128 + h*16 + d];
    }
    pooled[b][row] = pool * (1.f / 65536.f);
    __syncthreads();
    if (t < 32){
        int bb = t >> 4, j = t & 15;
        float s = 0.f;
        for (int c2 = 0; c2 < 128; c2++) s += sp_w1[j*128 + c2] * pooled[bb][c2];
        t1s[bb][j] = gelu_exact(s);
    }
    __syncthreads();
    if (t < 32){
        int bb = t >> 4, j = t & 15;
        float s = 0.f;
#pragma unroll
        for (int i = 0; i < 16; i++) s += sp_w2[j*16 + i] * t1s[bb][i];
        t2s[bb][j] = gelu_exact(s);
    }
    __syncthreads();
    {
        int bb = t >> 7, ch = t & 127;
        float s = 0.f;
#pragma unroll
        for (int j = 0; j < 16; j++) s += sp_w3[ch*16 + j] * t2s[bb][j];
        g_spec[bb*128 + ch] = 1.f / (1.f + expf(-s));
    }
}

// z = blockdiag(attn) @ v + spec * dwconv3x3(y)
__global__ void __launch_bounds__(256) k5a_z(const float* __restrict__ y,
                                             const float* __restrict__ dw_w){
    int tid = threadIdx.x;
    int r = blockIdx.x, b = blockIdx.y;
    __shared__ float s_attn[2048];
    __shared__ float s_spec[128];
    __shared__ float s_dw[128][9];
    for (int i = tid; i < 2048; i += 256) s_attn[i] = g_attn[b*2048 + i];
    for (int i = tid; i < 1152; i += 256) (&s_dw[0][0])[i] = dw_w[i];
    if (tid < 128) s_spec[tid] = g_spec[b*128 + tid];
    __syncthreads();

    for (int h = 0; h < 8; h++){
        float vv[16];
#pragma unroll
        for (int d = 0; d < 16; d++)
            vv[d] = g_v2[((size_t)b*128 + h*16 + d) * NTOT + r*256 + tid];
        for (int c = 0; c < 16; c++){
            int ch = h*16 + c;
            const float* ybase = y + ((size_t)b*128 + ch) * NTOT;
            float dv = conv_row(r > 0,   ybase + (size_t)(r-1)*256, tid, s_dw[ch][0], s_dw[ch][1], s_dw[ch][2])
                     + conv_row(1,       ybase + (size_t)r*256,     tid, s_dw[ch][3], s_dw[ch][4], s_dw[ch][5])
                     + conv_row(r < 255, ybase + (size_t)(r+1)*256, tid, s_dw[ch][6], s_dw[ch][7], s_dw[ch][8]);
            float z = s_spec[ch] * dv;
            const float* arow = &s_attn[ch * 16];
#pragma unroll
            for (int d = 0; d < 16; d++) z += arow[d] * vv[d];
            g_z[((size_t)b*128 + ch) * NTOT + r*256 + tid] = z;
        }
    }
}

extern "C" void kernel_launch(void* const* d_in, const int* in_sizes, int n_in,
                              void* d_out, int out_size){
    const float* x        = (const float*)d_in[0];
    const float* y        = (const float*)d_in[1];
    const float* qkv_w    = (const float*)d_in[2];
    const float* qkv_dw_w = (const float*)d_in[3];
    const float* proj_w   = (const float*)d_in[4];
    const float* sa_w1    = (const float*)d_in[5];
    const float* sa_w2    = (const float*)d_in[6];
    const float* sa_w3    = (const float*)d_in[7];
    const float* sp_w1    = (const float*)d_in[8];
    const float* sp_w2    = (const float*)d_in[9];
    const float* sp_w3    = (const float*)d_in[10];
    const float* dw_w     = (const float*)d_in[11];
    const float* temp     = (const float*)d_in[12];
    float* out = (float*)d_out;

    u64 *wq2, *wp2;
    float *qkv1, *z;
    cudaGetSymbolAddress((void**)&wq2,  g_wq2);
    cudaGetSymbolAddress((void**)&wp2,  g_wp2);
    cudaGetSymbolAddress((void**)&qkv1, g_qkv1);
    cudaGetSymbolAddress((void**)&z,    g_z);

    k_prep<<<276, 256>>>(qkv_w, proj_w);
    k_sa<<<dim3(64, 2), 256>>>(y, sa_w1, sa_w2, sa_w3);
    k_gemm<<<dim3(512, 3, 2), 256>>>(wq2, x, qkv1, 384);
    k2_dw<<<dim3(256, 8, 2), 256>>>(qkv_dw_w);
    k4_small<<<1, 256>>>(sp_w1, sp_w2, sp_w3, temp);
    k5a_z<<<dim3(256, 2), 256>>>(y, dw_w);
    k_gemm<<<dim3(512, 1, 2), 256>>>(wp2, z, out, 128);
}

// round 5
// speedup vs baseline: 1.3998x; 1.3998x over previous
#include <cuda_runtime.h>
#include <cstdint>

typedef unsigned long long u64;
#define NTOT 65536
#define BATCH 2

__device__ __align__(16) float g_qkv1[(size_t)BATCH*384*NTOT];
__device__ __align__(16) float g_sa  [(size_t)BATCH*NTOT];
__device__ __align__(16) float g_v2  [(size_t)BATCH*128*NTOT];
__device__ __align__(16) float g_z   [(size_t)BATCH*128*NTOT];
__device__ float g_S[4096];
__device__ float g_ssq_q[256];
__device__ float g_ssq_k[256];
__device__ float g_sumv[256];
__device__ float g_attn[4096];
__device__ float g_spec[256];
__device__ __align__(16) u64 g_wq2[128*384];
__device__ __align__(16) u64 g_wp2[128*128];

__device__ __forceinline__ void fma2(u64 &d, u64 a, u64 b){
    asm("fma.rn.f32x2 %0, %1, %2, %0;" : "+l"(d) : "l"(a), "l"(b));
}
__device__ __forceinline__ float2 unpack2(u64 v){
    float2 r; asm("mov.b64 {%0, %1}, %2;" : "=f"(r.x), "=f"(r.y) : "l"(v)); return r;
}
__device__ __forceinline__ void cp_async16(void* sdst, const void* gsrc){
    unsigned s = (unsigned)__cvta_generic_to_shared(sdst);
    asm volatile("cp.async.cg.shared.global [%0], [%1], 16;" :: "r"(s), "l"(gsrc));
}
__device__ __forceinline__ void cp_commit(){ asm volatile("cp.async.commit_group;"); }
__device__ __forceinline__ void cp_wait0(){ asm volatile("cp.async.wait_group 0;"); }
__device__ __forceinline__ float gelu_exact(float x){
    return 0.5f * x * (1.0f + erff(x * 0.70710678118654752f));
}

// 4-wide row stencil: thread owns cols 4t..4t+3 (t = tid&63, two warps per 256-col row).
// One LDG.128 + 2 SHFL per row; warp-edge cols patched with predicated scalar loads.
__device__ __forceinline__ void conv_acc4(float4& o, int valid, const float* row, int t,
                                          float w0, float w1, float w2){
    if (!valid) return;
    float4 a = __ldg((const float4*)(row + 4*t));
    float lf = __shfl_up_sync(0xffffffffu, a.w, 1);
    float rt = __shfl_down_sync(0xffffffffu, a.x, 1);
    int lane = t & 31;
    if (lane == 0)  lf = (t == 32) ? __ldg(row + 127) : 0.f;
    if (lane == 31) rt = (t == 31) ? __ldg(row + 128) : 0.f;
    o.x += w0*lf  + w1*a.x + w2*a.y;
    o.y += w0*a.x + w1*a.y + w2*a.z;
    o.z += w0*a.y + w1*a.z + w2*a.w;
    o.w += w0*a.z + w1*a.w + w2*rt;
}
__device__ __forceinline__ float4 conv3x4(const float* base, int r, int t, const float* w){
    float4 o = make_float4(0.f, 0.f, 0.f, 0.f);
    conv_acc4(o, r > 0,   base + (size_t)(r-1)*256, t, w[0], w[1], w[2]);
    conv_acc4(o, 1,       base + (size_t)r*256,     t, w[3], w[4], w[5]);
    conv_acc4(o, r < 255, base + (size_t)(r+1)*256, t, w[6], w[7], w[8]);
    return o;
}

__global__ void k_prep(const float* __restrict__ qkv_w, const float* __restrict__ proj_w){
    int idx = blockIdx.x * 256 + threadIdx.x;
    if (idx < 49152){
        int o = idx % 384, i = idx / 384;
        unsigned b = __float_as_uint(qkv_w[o*128 + i]);
        g_wq2[idx] = ((u64)b << 32) | (u64)b;
    } else if (idx < 65536){
        int k = idx - 49152;
        int i = k >> 7, o = k & 127;
        unsigned b = __float_as_uint(proj_w[o*128 + i]);
        g_wp2[k] = ((u64)b << 32) | (u64)b;
    } else {
        int j = idx - 65536;
        if (j < 4096) g_S[j] = 0.f;
        else if (j < 4352) g_ssq_q[j-4096] = 0.f;
        else if (j < 4608) g_ssq_k[j-4352] = 0.f;
        else if (j < 4864) g_sumv [j-4608] = 0.f;
    }
}

__global__ void __launch_bounds__(256) k_sa(const float* __restrict__ y,
                                            const float* __restrict__ w1,
                                            const float* __restrict__ w2,
                                            const float* __restrict__ w3){
    __shared__ float sW1[128][16];
    __shared__ float sW2[16][16];
    __shared__ float sW3[16];
    int tid = threadIdx.x;
    int b = blockIdx.y;
    for (int i = tid; i < 2048; i += 256){ int c = i >> 4, j = i & 15; sW1[c][j] = w1[j*128 + c]; }
    (&sW2[0][0])[tid] = w2[tid];
    if (tid < 16) sW3[tid] = w3[tid];
    __syncthreads();

    int n0 = (blockIdx.x * 256 + tid) * 4;
    float acc[4][16];
#pragma unroll
    for (int p = 0; p < 4; p++)
#pragma unroll
        for (int j = 0; j < 16; j++) acc[p][j] = 0.f;

    const float* yb = y + (size_t)b * 128 * NTOT + n0;
    for (int c = 0; c < 128; c++){
        float4 yv = *(const float4*)(yb + (size_t)c * NTOT);
#pragma unroll
        for (int j = 0; j < 16; j++){
            float w = sW1[c][j];
            acc[0][j] += w * yv.x; acc[1][j] += w * yv.y;
            acc[2][j] += w * yv.z; acc[3][j] += w * yv.w;
        }
    }
    float out[4];
#pragma unroll
    for (int p = 0; p < 4; p++){
        float t2[16];
#pragma unroll
        for (int i = 0; i < 16; i++){
            float s = 0.f;
#pragma unroll
            for (int j = 0; j < 16; j++) s += sW2[i][j] * fmaxf(acc[p][j], 0.f);
            t2[i] = fmaxf(s, 0.f);
        }
        float s3 = 0.f;
#pragma unroll
        for (int j = 0; j < 16; j++) s3 += sW3[j] * t2[j];
        out[p] = 1.f / (1.f + expf(-s3));
    }
    *(float4*)(g_sa + (size_t)b * NTOT + n0) = make_float4(out[0], out[1], out[2], out[3]);
}

// C[M,N] = W[M,128] @ X[128,N] per batch; FFMA2 register tile 8x8, cp.async double buffer
__global__ void __launch_bounds__(256, 2) k_gemm(const u64* __restrict__ w2,
                                                 const float* __restrict__ X,
                                                 float* __restrict__ C, int M){
    __shared__ u64 ws[2][16][128];
    __shared__ u64 xs[2][16][64];

    int tid = threadIdx.x;
    int b = blockIdx.z;
    int obase = blockIdx.y * 128;
    int nbase = blockIdx.x * 128;
    const float* x = X + (size_t)b * 128 * NTOT;
    float* c = C + (size_t)b * M * NTOT;
    int to8 = (tid >> 4) * 8;
    int tn4 = (tid & 15) * 4;

    auto load_chunk = [&](int kc, int buf){
#pragma unroll
        for (int t = 0; t < 4; t++){
            int e = t * 256 + tid;
            int k = e >> 6;
            int o = (2 * e) & 127;
            cp_async16(&ws[buf][k][o], w2 + (size_t)(kc*16 + k) * M + obase + o);
        }
#pragma unroll
        for (int t = 0; t < 2; t++){
            int e = t * 256 + tid;
            int k = e >> 5;
            int p = (2 * e) & 63;
            cp_async16(&xs[buf][k][p], x + (size_t)(kc*16 + k) * NTOT + nbase + 2*p);
        }
        cp_commit();
    };

    u64 acc[8][4];
#pragma unroll
    for (int o = 0; o < 8; o++)
#pragma unroll
        for (int p = 0; p < 4; p++) acc[o][p] = 0ULL;

    load_chunk(0, 0);
    cp_wait0(); __syncthreads();

    for (int kc = 0; kc < 8; kc++){
        int buf = kc & 1;
        if (kc < 7) load_chunk(kc + 1, buf ^ 1);
#pragma unroll
        for (int k = 0; k < 16; k++){
            u64 wv[8], xv[4];
#pragma unroll
            for (int j = 0; j < 4; j++){
                ulonglong2 t = *(const ulonglong2*)&ws[buf][k][to8 + 2*j];
                wv[2*j] = t.x; wv[2*j+1] = t.y;
            }
            {
                ulonglong2 t0 = *(const ulonglong2*)&xs[buf][k][tn4];
                ulonglong2 t1 = *(const ulonglong2*)&xs[buf][k][tn4 + 2];
                xv[0] = t0.x; xv[1] = t0.y; xv[2] = t1.x; xv[3] = t1.y;
            }
#pragma unroll
            for (int o = 0; o < 8; o++)
#pragma unroll
                for (int p = 0; p < 4; p++)
                    fma2(acc[o][p], wv[o], xv[p]);
        }
        if (kc < 7){ cp_wait0(); __syncthreads(); }
    }

#pragma unroll
    for (int o = 0; o < 8; o++){
        float2 f0 = unpack2(acc[o][0]), f1 = unpack2(acc[o][1]);
        float2 f2 = unpack2(acc[o][2]), f3 = unpack2(acc[o][3]);
        float* dst = c + (size_t)(obase + to8 + o) * NTOT + nbase + (tid & 15) * 8;
        *(float4*)(dst)     = make_float4(f0.x, f0.y, f1.x, f1.y);
        *(float4*)(dst + 4) = make_float4(f2.x, f2.y, f3.x, f3.y);
    }
}

// fused dwconv3x3 + sa gate + (S=q.k^T, ||q||^2, ||k||^2, sum v) reductions + v write
// 4 thread-groups of 64; each group owns one channel per iteration, 4 cols/thread.
__global__ void __launch_bounds__(256) k2_dw(const float* __restrict__ qkv_dw_w){
    int tid = threadIdx.x;
    int r = blockIdx.x, h = blockIdx.y, b = blockIdx.z;
    int g = tid >> 6, t = tid & 63;
    __shared__ __align__(16) float qs[16][268];
    __shared__ __align__(16) float ks[16][268];
    __shared__ float sdw[48][9];
    __shared__ __align__(16) float s_sa[256];
    __shared__ float s_ssq_q[16], s_ssq_k[16], s_vsum[16];

    if (tid < 64)
        *(float4*)(s_sa + 4*tid) = *(const float4*)(g_sa + (size_t)b*NTOT + r*256 + 4*tid);
    for (int idx = tid; idx < 432; idx += 256){
        int lc = idx / 9, j = idx % 9;
        int ch = (lc < 16) ? (h*16 + lc) : (lc < 32 ? (128 + h*16 + (lc-16)) : (256 + h*16 + (lc-32)));
        sdw[lc][j] = qkv_dw_w[ch*9 + j];
    }
    if (tid < 16){ s_ssq_q[tid] = 0.f; s_ssq_k[tid] = 0.f; s_vsum[tid] = 0.f; }
    __syncthreads();

    float4 sa4 = *(const float4*)(s_sa + 4*t);
    int lane = tid & 31;

    for (int lc0 = 0; lc0 < 48; lc0 += 4){
        int lc = lc0 + g;
        int ch = (lc < 16) ? (h*16 + lc) : (lc < 32 ? (128 + h*16 + (lc-16)) : (256 + h*16 + (lc-32)));
        const float* base = g_qkv1 + ((size_t)b*384 + ch) * NTOT;
        float4 v = conv3x4(base, r, t, sdw[lc]);
        if (lc < 16){
            v.x *= sa4.x; v.y *= sa4.y; v.z *= sa4.z; v.w *= sa4.w;
            *(float4*)&qs[lc][4*t] = v;
            float sq = v.x*v.x + v.y*v.y + v.z*v.z + v.w*v.w;
#pragma unroll
            for (int o = 16; o; o >>= 1) sq += __shfl_down_sync(0xffffffffu, sq, o);
            if (lane == 0) atomicAdd(&s_ssq_q[lc], sq);
        } else if (lc < 32){
            *(float4*)&ks[lc-16][4*t] = v;
            float sq = v.x*v.x + v.y*v.y + v.z*v.z + v.w*v.w;
#pragma unroll
            for (int o = 16; o; o >>= 1) sq += __shfl_down_sync(0xffffffffu, sq, o);
            if (lane == 0) atomicAdd(&s_ssq_k[lc-16], sq);
        } else {
            *(float4*)(g_v2 + ((size_t)b*128 + h*16 + (lc-32)) * NTOT + r*256 + 4*t) = v;
            float sv = v.x + v.y + v.z + v.w;
#pragma unroll
            for (int o = 16; o; o >>= 1) sv += __shfl_down_sync(0xffffffffu, sv, o);
            if (lane == 0) atomicAdd(&s_vsum[lc-32], sv);
        }
    }
    __syncthreads();

    // S[c][d] partial over this row, float4 dot products
    int c = tid >> 4, d = tid & 15;
    float s = 0.f;
#pragma unroll 8
    for (int i = 0; i < 64; i++){
        float4 qv = *(const float4*)&qs[c][4*i];
        float4 kv = *(const float4*)&ks[d][4*i];
        s += qv.x*kv.x + qv.y*kv.y + qv.z*kv.z + qv.w*kv.w;
    }
    atomicAdd(&g_S[((b*8 + h)*16 + c)*16 + d], s);

    if (tid < 16){
        atomicAdd(&g_ssq_q[b*128 + h*16 + tid], s_ssq_q[tid]);
        atomicAdd(&g_ssq_k[b*128 + h*16 + tid], s_ssq_k[tid]);
        atomicAdd(&g_sumv [b*128 + h*16 + tid], s_vsum[tid]);
    }
}

// softmax + spectral MLP (one block, 256 threads)
__global__ void k4_small(const float* __restrict__ sp_w1, const float* __restrict__ sp_w2,
                         const float* __restrict__ sp_w3, const float* __restrict__ temp){
    __shared__ float pooled[2][128];
    __shared__ float t1s[2][16], t2s[2][16];
    int t = threadIdx.x;
    int b = t >> 7, row = t & 127, h = row >> 4, c = row & 15;

    float nq = fmaxf(sqrtf(g_ssq_q[b*128 + row]), 1e-12f);
    float tmp = temp[h];
    float logits[16];
    float mx = -1e30f;
#pragma unroll
    for (int d = 0; d < 16; d++){
        float nk = fmaxf(sqrtf(g_ssq_k[b*128 + h*16 + d]), 1e-12f);
        float L = g_S[((b*8 + h)*16 + c)*16 + d] / (nq * nk) * tmp;
        logits[d] = L; mx = fmaxf(mx, L);
    }
    float se = 0.f;
#pragma unroll
    for (int d = 0; d < 16; d++){ float e = expf(logits[d] - mx); logits[d] = e; se += e; }
    float inv = 1.f / se;
    float pool = 0.f;
#pragma unroll
    for (int d = 0; d < 16; d++){
        float a = logits[d] * inv;
        g_attn[b*2048 + (h*16 + c)*16 + d] = a;
        pool += a * g_sumv[b*128 + h*16 + d];
    }
    pooled[b][row] = pool * (1.f / 65536.f);
    __syncthreads();
    if (t < 32){
        int bb = t >> 4, j = t & 15;
        float s = 0.f;
        for (int c2 = 0; c2 < 128; c2++) s += sp_w1[j*128 + c2] * pooled[bb][c2];
        t1s[bb][j] = gelu_exact(s);
    }
    __syncthreads();
    if (t < 32){
        int bb = t >> 4, j = t & 15;
        float s = 0.f;
#pragma unroll
        for (int i = 0; i < 16; i++) s += sp_w2[j*16 + i] * t1s[bb][i];
        t2s[bb][j] = gelu_exact(s);
    }
    __syncthreads();
    {
        int bb = t >> 7, ch = t & 127;
        float s = 0.f;
#pragma unroll
        for (int j = 0; j < 16; j++) s += sp_w3[ch*16 + j] * t2s[bb][j];
        g_spec[bb*128 + ch] = 1.f / (1.f + expf(-s));
    }
}

// z = blockdiag(attn) @ v + spec * dwconv3x3(y); 4-wide, v tile staged in smem per head
__global__ void __launch_bounds__(256) k5a_z(const float* __restrict__ y,
                                             const float* __restrict__ dw_w){
    int tid = threadIdx.x;
    int r = blockIdx.x, b = blockIdx.y;
    int g = tid >> 6, t = tid & 63;
    __shared__ float s_attn[2048];
    __shared__ float s_spec[128];
    __shared__ float s_dw[128][9];
    __shared__ __align__(16) float sv[16][256];
    for (int i = tid; i < 2048; i += 256) s_attn[i] = g_attn[b*2048 + i];
    for (int i = tid; i < 1152; i += 256) (&s_dw[0][0])[i] = dw_w[i];
    if (tid < 128) s_spec[tid] = g_spec[b*128 + tid];
    __syncthreads();

    for (int h = 0; h < 8; h++){
        // stage v tile [16][256] cooperatively
        for (int i = tid; i < 1024; i += 256){
            int d = i >> 6, p = i & 63;
            *(float4*)&sv[d][4*p] =
                *(const float4*)(g_v2 + ((size_t)b*128 + h*16 + d) * NTOT + r*256 + 4*p);
        }
        __syncthreads();
#pragma unroll
        for (int cc = 0; cc < 4; cc++){
            int c = cc*4 + g;
            int ch = h*16 + c;
            const float* ybase = y + ((size_t)b*128 + ch) * NTOT;
            float4 z = conv3x4(ybase, r, t, s_dw[ch]);
            float sp = s_spec[ch];
            z.x *= sp; z.y *= sp; z.z *= sp; z.w *= sp;
            const float* arow = &s_attn[ch * 16];
#pragma unroll
            for (int d = 0; d < 16; d++){
                float a = arow[d];
                float4 vd = *(const float4*)&sv[d][4*t];
                z.x += a*vd.x; z.y += a*vd.y; z.z += a*vd.z; z.w += a*vd.w;
            }
            *(float4*)(g_z + ((size_t)b*128 + ch) * NTOT + r*256 + 4*t) = z;
        }
        __syncthreads();
    }
}

extern "C" void kernel_launch(void* const* d_in, const int* in_sizes, int n_in,
                              void* d_out, int out_size){
    const float* x        = (const float*)d_in[0];
    const float* y        = (const float*)d_in[1];
    const float* qkv_w    = (const float*)d_in[2];
    const float* qkv_dw_w = (const float*)d_in[3];
    const float* proj_w   = (const float*)d_in[4];
    const float* sa_w1    = (const float*)d_in[5];
    const float* sa_w2    = (const float*)d_in[6];
    const float* sa_w3    = (const float*)d_in[7];
    const float* sp_w1    = (const float*)d_in[8];
    const float* sp_w2    = (const float*)d_in[9];
    const float* sp_w3    = (const float*)d_in[10];
    const float* dw_w     = (const float*)d_in[11];
    const float* temp     = (const float*)d_in[12];
    float* out = (float*)d_out;

    u64 *wq2, *wp2;
    float *qkv1, *z;
    cudaGetSymbolAddress((void**)&wq2,  g_wq2);
    cudaGetSymbolAddress((void**)&wp2,  g_wp2);
    cudaGetSymbolAddress((void**)&qkv1, g_qkv1);
    cudaGetSymbolAddress((void**)&z,    g_z);

    k_prep<<<276, 256>>>(qkv_w, proj_w);
    k_sa<<<dim3(64, 2), 256>>>(y, sa_w1, sa_w2, sa_w3);
    k_gemm<<<dim3(512, 3, 2), 256>>>(wq2, x, qkv1, 384);
    k2_dw<<<dim3(256, 8, 2), 256>>>(qkv_dw_w);
    k4_small<<<1, 256>>>(sp_w1, sp_w2, sp_w3, temp);
    k5a_z<<<dim3(256, 2), 256>>>(y, dw_w);
    k_gemm<<<dim3(512, 1, 2), 256>>>(wp2, z, out, 128);
}